// round 16
// baseline (speedup 1.0000x reference)
#include <cuda_runtime.h>
#include <cuda_fp16.h>
#include <cstdint>
#include <cstddef>

// Problem constants (fixed by the dataset)
#define N_TOK   1048576
#define B_SEG   4096
#define D_IN    256
#define H_MLP   128
#define N_TILES (N_TOK / 16)      // 65536 tiles of 16 tokens
#define GRID_LG 152

// smem layout for logits kernel
//  [0, 65536)        : W1 fp16 B-fragments, uint4 x (16 kt * 8 np * 32 ln)
//  [65536, 66560)    : 128 x float2 {b1, W2}
//  [66560, ...)      : per-warp staging for fp16(x): 16 warps x 16 rows x 132 half2
#define FRAG4_ELEMS (16 * 8 * 32)
#define SM_PW       (FRAG4_ELEMS * 16)
#define SM_STAGE    (SM_PW + H_MLP * 8)
#define STAGE_ROW   132                       // 128 data half2 + 4 pad (16B-aligned rows)
#define STAGE_WARP  (16 * STAGE_ROW)
#define SMEM_LG     (SM_STAGE + 16 * STAGE_WARP * 4)

__device__ float g_denom[B_SEG];

// ---------------------------------------------------------------------------
// helpers
// ---------------------------------------------------------------------------
__device__ __forceinline__ uint32_t pack_f16x2(float lo, float hi) {
    // lower 16 bits = fp16(lo), upper = fp16(hi)
    uint32_t r;
    asm("cvt.rn.f16x2.f32 %0, %1, %2;" : "=r"(r) : "f"(hi), "f"(lo));
    return r;
}

__device__ __forceinline__ void mma_f16(float d[4],
                                        uint32_t a0, uint32_t a1, uint32_t a2, uint32_t a3,
                                        uint32_t b0, uint32_t b1) {
    asm volatile(
        "mma.sync.aligned.m16n8k16.row.col.f32.f16.f16.f32 "
        "{%0,%1,%2,%3}, {%4,%5,%6,%7}, {%8,%9}, {%0,%1,%2,%3};\n"
        : "+f"(d[0]), "+f"(d[1]), "+f"(d[2]), "+f"(d[3])
        : "r"(a0), "r"(a1), "r"(a2), "r"(a3), "r"(b0), "r"(b1));
}

__device__ __forceinline__ float tanh_fast(float v) {
    float r;
    asm("tanh.approx.f32 %0, %1;" : "=f"(r) : "f"(v));
    return r;
}

// ---------------------------------------------------------------------------
// Pass 0: zero the atomic accumulation targets (ctx region of d_out + denom).
// ---------------------------------------------------------------------------
__global__ void zero_kernel(float* __restrict__ ctx) {
    int i = blockIdx.x * blockDim.x + threadIdx.x;
    if (i < B_SEG * D_IN) ctx[i] = 0.0f;
    if (i < B_SEG) g_denom[i] = 0.0f;
}

// ---------------------------------------------------------------------------
// Pass 1 (fused): per 16-token warp tile
//   s  = tanh(x @ W1 + b1) @ W2 + b2      (single fp16 MMA GEMM)
//   z  = exp(s)                            -> written to sw (normalized later)
//   atomically accumulate ctx[seg] += z * fp16(x),  denom[seg] += z
// exp without max-subtraction is safe: |s| <= sum|W2| ~= 9  =>  z <= ~8100.
// ---------------------------------------------------------------------------
__global__ __launch_bounds__(512, 1)
void logits_pool_kernel(const float* __restrict__ x,
                        const int* __restrict__ seg,
                        const float* __restrict__ W1,
                        const float* __restrict__ b1,
                        const float* __restrict__ W2,
                        const float* __restrict__ b2,
                        float* __restrict__ sw,
                        float* __restrict__ ctx) {
    extern __shared__ unsigned char smem_raw[];
    uint4*  frag4 = reinterpret_cast<uint4*>(smem_raw);
    float2* pw    = reinterpret_cast<float2*>(smem_raw + SM_PW);

    const int tid = threadIdx.x;

    // --- pack W1 (fp16) into paired B-fragment layout: uint4 = {nt=2np, nt=2np+1} ---
    for (int e = tid; e < FRAG4_ELEMS; e += 512) {
        int kt = e >> 8;              // 0..15
        int np = (e >> 5) & 7;        // 0..7 (nt pair)
        int ln = e & 31;
        int k0 = kt * 16 + (ln & 3) * 2;
        int nn = np * 16 + (ln >> 2);       // column for nt = 2np
        float v0 = W1[(k0    ) * H_MLP + nn];
        float v1 = W1[(k0 + 1) * H_MLP + nn];
        float v2 = W1[(k0 + 8) * H_MLP + nn];
        float v3 = W1[(k0 + 9) * H_MLP + nn];
        float u0 = W1[(k0    ) * H_MLP + nn + 8];
        float u1 = W1[(k0 + 1) * H_MLP + nn + 8];
        float u2 = W1[(k0 + 8) * H_MLP + nn + 8];
        float u3 = W1[(k0 + 9) * H_MLP + nn + 8];
        frag4[e] = make_uint4(pack_f16x2(v0, v1), pack_f16x2(v2, v3),
                              pack_f16x2(u0, u1), pack_f16x2(u2, u3));
    }
    for (int n = tid; n < H_MLP; n += 512)
        pw[n] = make_float2(b1[n], W2[n]);
    const float bias2 = b2[0];
    __syncthreads();

    const int warp  = tid >> 5;
    const int lane  = tid & 31;
    const int g     = lane >> 2;          // row within 8-row groups
    const int cbase = (lane & 3) * 2;     // col pair base
    const int cb2   = lane & 3;           // half2 column index within 8

    // pooling feature map for the LDS.128 read at half2 col c0 = lane*4 + j
    int fmap[4];
#pragma unroll
    for (int j = 0; j < 4; j++) {
        int c = lane * 4 + j;
        fmap[j] = 16 * (c >> 3) + ((c & 4) << 1) + ((c & 3) << 1);
    }

    __half2* stage = reinterpret_cast<__half2*>(smem_raw + SM_STAGE) + warp * STAGE_WARP;

    for (int tile = blockIdx.x * 16 + warp; tile < N_TILES; tile += GRID_LG * 16) {
        const float* xr0 = x + (size_t)(tile * 16 + g) * D_IN;
        const float* xr1 = xr0 + 8 * D_IN;

        // segment ids for this tile's 16 tokens (broadcast later via shfl)
        int sgid = 0;
        if (lane < 16) sgid = __ldg(seg + tile * 16 + lane);

        float acc[64];
#pragma unroll
        for (int i = 0; i < 64; i++) acc[i] = 0.0f;

        // prefetch kt = 0 (streaming: x is read exactly once)
        float2 q0 = __ldcs(reinterpret_cast<const float2*>(xr0 + cbase));
        float2 q1 = __ldcs(reinterpret_cast<const float2*>(xr0 + cbase + 8));
        float2 q2 = __ldcs(reinterpret_cast<const float2*>(xr1 + cbase));
        float2 q3 = __ldcs(reinterpret_cast<const float2*>(xr1 + cbase + 8));

#pragma unroll 1
        for (int kt = 0; kt < 16; kt++) {
            float2 c0 = q0, c1 = q1, c2 = q2, c3 = q3;
            if (kt < 15) {
                int c = (kt + 1) * 16 + cbase;
                q0 = __ldcs(reinterpret_cast<const float2*>(xr0 + c));
                q1 = __ldcs(reinterpret_cast<const float2*>(xr0 + c + 8));
                q2 = __ldcs(reinterpret_cast<const float2*>(xr1 + c));
                q3 = __ldcs(reinterpret_cast<const float2*>(xr1 + c + 8));
            }
            // A fragments: a0=(r0,k0-7) a1=(r1,k0-7) a2=(r0,k8-15) a3=(r1,k8-15)
            uint32_t ah0 = pack_f16x2(c0.x, c0.y);
            uint32_t ah1 = pack_f16x2(c2.x, c2.y);
            uint32_t ah2 = pack_f16x2(c1.x, c1.y);
            uint32_t ah3 = pack_f16x2(c3.x, c3.y);

            // stage fp16(x) for the fused pooling phase
            {
                int col = kt * 8 + cb2;
                stage[g * STAGE_ROW + col]           = *reinterpret_cast<__half2*>(&ah0);
                stage[g * STAGE_ROW + col + 4]       = *reinterpret_cast<__half2*>(&ah2);
                stage[(g + 8) * STAGE_ROW + col]     = *reinterpret_cast<__half2*>(&ah1);
                stage[(g + 8) * STAGE_ROW + col + 4] = *reinterpret_cast<__half2*>(&ah3);
            }

            const uint4* bp = frag4 + kt * 256 + lane;
#pragma unroll
            for (int np = 0; np < 8; np++) {
                uint4 bb = bp[np * 32];             // one conflict-free LDS.128
                mma_f16(&acc[(2 * np    ) * 4], ah0, ah1, ah2, ah3, bb.x, bb.y);
                mma_f16(&acc[(2 * np + 1) * 4], ah0, ah1, ah2, ah3, bb.z, bb.w);
            }
        }

        // epilogue: s = sum_n tanh(h + b1) * W2  ->  z = exp(s + b2)
        float p0 = 0.0f, p1 = 0.0f;
#pragma unroll
        for (int nt = 0; nt < 16; nt++) {
            int n0 = nt * 8 + cbase;
            float2 w0 = pw[n0];
            float2 w1 = pw[n0 + 1];
            p0 += tanh_fast(acc[nt * 4 + 0] + w0.x) * w0.y;
            p0 += tanh_fast(acc[nt * 4 + 1] + w1.x) * w1.y;
            p1 += tanh_fast(acc[nt * 4 + 2] + w0.x) * w0.y;
            p1 += tanh_fast(acc[nt * 4 + 3] + w1.x) * w1.y;
        }
        p0 += __shfl_xor_sync(0xffffffffu, p0, 1);
        p0 += __shfl_xor_sync(0xffffffffu, p0, 2);
        p1 += __shfl_xor_sync(0xffffffffu, p1, 1);
        p1 += __shfl_xor_sync(0xffffffffu, p1, 2);

        const float z0 = __expf(p0 + bias2);        // row g
        const float z1 = __expf(p1 + bias2);        // row g + 8
        if ((lane & 3) == 0) {
            int r = tile * 16 + g;
            __stcs(sw + r,     z0);
            __stcs(sw + r + 8, z1);
        }
        __syncwarp();   // stage fully written by all lanes before cross-lane reads

        // ---- fused pooling: ctx[sid] += z * x_fp16, denom[sid] += z ----
        // lane reads one contiguous uint4 (4 half2) per token: cols lane*4..+3
        {
            float facc[8];
#pragma unroll
            for (int j = 0; j < 8; j++) facc[j] = 0.0f;
            float zsum = 0.0f;
            int cur = __shfl_sync(0xffffffffu, sgid, 0);
            const uint4* srow = reinterpret_cast<const uint4*>(stage) + lane;

#pragma unroll 1
            for (int tok = 0; tok < 16; tok++) {
                int sid_t = __shfl_sync(0xffffffffu, sgid, tok);
                float zt = (tok < 8)
                    ? __shfl_sync(0xffffffffu, z0, tok * 4)
                    : __shfl_sync(0xffffffffu, z1, (tok - 8) * 4);
                if (sid_t != cur) {
                    // flush previous segment group
                    float* cp = ctx + (size_t)cur * D_IN;
#pragma unroll
                    for (int j = 0; j < 4; j++) {
                        atomicAdd(cp + fmap[j],     facc[2 * j]);
                        atomicAdd(cp + fmap[j] + 1, facc[2 * j + 1]);
                        facc[2 * j] = 0.0f; facc[2 * j + 1] = 0.0f;
                    }
                    if (lane == 0) atomicAdd(&g_denom[cur], zsum);
                    zsum = 0.0f;
                    cur = sid_t;
                }
                zsum += zt;
                uint4 v = srow[tok * (STAGE_ROW / 4)];   // one LDS.128, conflict-free
                float2 f0 = __half22float2(*reinterpret_cast<const __half2*>(&v.x));
                float2 f1 = __half22float2(*reinterpret_cast<const __half2*>(&v.y));
                float2 f2 = __half22float2(*reinterpret_cast<const __half2*>(&v.z));
                float2 f3 = __half22float2(*reinterpret_cast<const __half2*>(&v.w));
                facc[0] += zt * f0.x;  facc[1] += zt * f0.y;
                facc[2] += zt * f1.x;  facc[3] += zt * f1.y;
                facc[4] += zt * f2.x;  facc[5] += zt * f2.y;
                facc[6] += zt * f3.x;  facc[7] += zt * f3.y;
            }
            // final flush
            float* cp = ctx + (size_t)cur * D_IN;
#pragma unroll
            for (int j = 0; j < 4; j++) {
                atomicAdd(cp + fmap[j],     facc[2 * j]);
                atomicAdd(cp + fmap[j] + 1, facc[2 * j + 1]);
            }
            if (lane == 0) atomicAdd(&g_denom[cur], zsum);
        }
        __syncwarp();   // stage fully consumed before next iteration overwrites
    }
}

// ---------------------------------------------------------------------------
// Pass 2a: attention_weights[i] = z[i] / denom[seg[i]]
// ---------------------------------------------------------------------------
__global__ __launch_bounds__(256)
void norm_w_kernel(float* __restrict__ sw, const int* __restrict__ seg) {
    int i = blockIdx.x * blockDim.x + threadIdx.x;
    if (i >= N_TOK) return;
    float d = __ldg(&g_denom[__ldg(seg + i)]);
    __stcs(sw + i, __ldcs(sw + i) / d);
}

// ---------------------------------------------------------------------------
// Pass 2b: ctx[b,:] /= denom[b]   (empty segment -> 0, matching segment_sum)
// ---------------------------------------------------------------------------
__global__ __launch_bounds__(256)
void norm_ctx_kernel(float* __restrict__ ctx) {
    int i = blockIdx.x * blockDim.x + threadIdx.x;
    if (i >= B_SEG * D_IN) return;
    float d = g_denom[i >> 8];
    float v = ctx[i];
    ctx[i] = (d > 0.0f) ? v / d : 0.0f;
}

// ---------------------------------------------------------------------------
// launch: outputs are [context_vectors (B*D)] then [attention_weights (N)]
// ---------------------------------------------------------------------------
extern "C" void kernel_launch(void* const* d_in, const int* in_sizes, int n_in,
                              void* d_out, int out_size) {
    const float* x   = (const float*)d_in[0];
    const int*   seg = (const int*)d_in[1];
    const float* W1  = (const float*)d_in[2];
    const float* b1  = (const float*)d_in[3];
    const float* W2  = (const float*)d_in[4];
    const float* b2  = (const float*)d_in[5];

    float* ctx = (float*)d_out;                       // [B, D]
    float* sw  = ctx + (size_t)B_SEG * D_IN;          // [N] : z then weights

    cudaFuncSetAttribute(logits_pool_kernel,
                         cudaFuncAttributeMaxDynamicSharedMemorySize, SMEM_LG);

    zero_kernel<<<(B_SEG * D_IN + 511) / 512, 512>>>(ctx);
    logits_pool_kernel<<<GRID_LG, 512, SMEM_LG>>>(x, seg, W1, b1, W2, b2, sw, ctx);
    norm_w_kernel<<<N_TOK / 256, 256>>>(sw, seg);
    norm_ctx_kernel<<<(B_SEG * D_IN) / 256, 256>>>(ctx);
}

// round 17
// speedup vs baseline: 1.0462x; 1.0462x over previous
#include <cuda_runtime.h>
#include <cuda_fp16.h>
#include <cstdint>
#include <cstddef>

// Problem constants (fixed by the dataset)
#define N_TOK   1048576
#define B_SEG   4096
#define D_IN    256
#define H_MLP   128
#define N_TILES (N_TOK / 16)      // 65536 tiles of 16 tokens
#define GRID_LG 152

// smem layout for logits kernel
//  [0, 65536)        : W1 fp16 B-fragments, uint4 x (16 kt * 8 np * 32 ln)
//  [65536, 66560)    : 128 x float2 {b1, W2}
//  [66560, ...)      : per-warp staging for fp16(x): 16 warps x 16 rows x 132 half2
#define FRAG4_ELEMS (16 * 8 * 32)
#define SM_PW       (FRAG4_ELEMS * 16)
#define SM_STAGE    (SM_PW + H_MLP * 8)
#define STAGE_ROW   132                       // 128 data half2 + 4 pad (16B-aligned rows)
#define STAGE_WARP  (16 * STAGE_ROW)
#define SMEM_LG     (SM_STAGE + 16 * STAGE_WARP * 4)

__device__ float g_denom[B_SEG];

// ---------------------------------------------------------------------------
// helpers
// ---------------------------------------------------------------------------
__device__ __forceinline__ uint32_t pack_f16x2(float lo, float hi) {
    // lower 16 bits = fp16(lo), upper = fp16(hi)
    uint32_t r;
    asm("cvt.rn.f16x2.f32 %0, %1, %2;" : "=r"(r) : "f"(hi), "f"(lo));
    return r;
}

__device__ __forceinline__ void mma_f16(float d[4],
                                        uint32_t a0, uint32_t a1, uint32_t a2, uint32_t a3,
                                        uint32_t b0, uint32_t b1) {
    asm volatile(
        "mma.sync.aligned.m16n8k16.row.col.f32.f16.f16.f32 "
        "{%0,%1,%2,%3}, {%4,%5,%6,%7}, {%8,%9}, {%0,%1,%2,%3};\n"
        : "+f"(d[0]), "+f"(d[1]), "+f"(d[2]), "+f"(d[3])
        : "r"(a0), "r"(a1), "r"(a2), "r"(a3), "r"(b0), "r"(b1));
}

__device__ __forceinline__ float tanh_fast(float v) {
    float r;
    asm("tanh.approx.f32 %0, %1;" : "=f"(r) : "f"(v));
    return r;
}

// ---------------------------------------------------------------------------
// Pass 0: zero the atomic accumulation targets (ctx region of d_out + denom).
// ---------------------------------------------------------------------------
__global__ void zero_kernel(float* __restrict__ ctx) {
    int i = blockIdx.x * blockDim.x + threadIdx.x;
    if (i < B_SEG * D_IN) ctx[i] = 0.0f;
    if (i < B_SEG) g_denom[i] = 0.0f;
}

// ---------------------------------------------------------------------------
// Pass 1 (fused): per 16-token warp tile
//   s  = tanh(x @ W1 + b1) @ W2 + b2      (single fp16 MMA GEMM)
//   z  = exp(s)                            -> written to sw (normalized later)
//   atomically accumulate ctx[seg] += z * fp16(x),  denom[seg] += z
// exp without max-subtraction is safe: |s| <= sum|W2| ~= 9  =>  z <= ~8100.
// ---------------------------------------------------------------------------
__global__ __launch_bounds__(512, 1)
void logits_pool_kernel(const float* __restrict__ x,
                        const int* __restrict__ seg,
                        const float* __restrict__ W1,
                        const float* __restrict__ b1,
                        const float* __restrict__ W2,
                        const float* __restrict__ b2,
                        float* __restrict__ sw,
                        float* __restrict__ ctx) {
    extern __shared__ unsigned char smem_raw[];
    uint4*  frag4 = reinterpret_cast<uint4*>(smem_raw);
    float2* pw    = reinterpret_cast<float2*>(smem_raw + SM_PW);

    const int tid = threadIdx.x;

    // --- pack W1 (fp16) into paired B-fragment layout: uint4 = {nt=2np, nt=2np+1} ---
    for (int e = tid; e < FRAG4_ELEMS; e += 512) {
        int kt = e >> 8;              // 0..15
        int np = (e >> 5) & 7;        // 0..7 (nt pair)
        int ln = e & 31;
        int k0 = kt * 16 + (ln & 3) * 2;
        int nn = np * 16 + (ln >> 2);       // column for nt = 2np
        float v0 = W1[(k0    ) * H_MLP + nn];
        float v1 = W1[(k0 + 1) * H_MLP + nn];
        float v2 = W1[(k0 + 8) * H_MLP + nn];
        float v3 = W1[(k0 + 9) * H_MLP + nn];
        float u0 = W1[(k0    ) * H_MLP + nn + 8];
        float u1 = W1[(k0 + 1) * H_MLP + nn + 8];
        float u2 = W1[(k0 + 8) * H_MLP + nn + 8];
        float u3 = W1[(k0 + 9) * H_MLP + nn + 8];
        frag4[e] = make_uint4(pack_f16x2(v0, v1), pack_f16x2(v2, v3),
                              pack_f16x2(u0, u1), pack_f16x2(u2, u3));
    }
    for (int n = tid; n < H_MLP; n += 512)
        pw[n] = make_float2(b1[n], W2[n]);
    const float bias2 = b2[0];
    __syncthreads();

    const int warp  = tid >> 5;
    const int lane  = tid & 31;
    const int g     = lane >> 2;          // row within 8-row groups
    const int cbase = (lane & 3) * 2;     // col pair base
    const int cb2   = lane & 3;           // half2 column index within 8

    // pooling feature map: smem half2 col c = kt*8 + cb2*2 + sub holds
    // features {16*kt + cb2*2 + sub*8, +1}; pooling lane reads c = lane*4 + j
    int fmap[4];
#pragma unroll
    for (int j = 0; j < 4; j++) {
        int c = lane * 4 + j;
        fmap[j] = 16 * (c >> 3) + ((c >> 1) & 3) * 2 + (c & 1) * 8;
    }

    __half2* stage = reinterpret_cast<__half2*>(smem_raw + SM_STAGE) + warp * STAGE_WARP;

    for (int tile = blockIdx.x * 16 + warp; tile < N_TILES; tile += GRID_LG * 16) {
        const float* xr0 = x + (size_t)(tile * 16 + g) * D_IN;
        const float* xr1 = xr0 + 8 * D_IN;

        // segment ids for this tile's 16 tokens (broadcast later via shfl)
        int sgid = 0;
        if (lane < 16) sgid = __ldg(seg + tile * 16 + lane);

        float acc[64];
#pragma unroll
        for (int i = 0; i < 64; i++) acc[i] = 0.0f;

        // prefetch kt = 0
        float2 q0 = *reinterpret_cast<const float2*>(xr0 + cbase);
        float2 q1 = *reinterpret_cast<const float2*>(xr0 + cbase + 8);
        float2 q2 = *reinterpret_cast<const float2*>(xr1 + cbase);
        float2 q3 = *reinterpret_cast<const float2*>(xr1 + cbase + 8);

#pragma unroll 1
        for (int kt = 0; kt < 16; kt++) {
            float2 c0 = q0, c1 = q1, c2 = q2, c3 = q3;
            if (kt < 15) {
                int c = (kt + 1) * 16 + cbase;
                q0 = *reinterpret_cast<const float2*>(xr0 + c);
                q1 = *reinterpret_cast<const float2*>(xr0 + c + 8);
                q2 = *reinterpret_cast<const float2*>(xr1 + c);
                q3 = *reinterpret_cast<const float2*>(xr1 + c + 8);
            }
            // A fragments: a0=(r0,k0-7) a1=(r1,k0-7) a2=(r0,k8-15) a3=(r1,k8-15)
            uint32_t ah0 = pack_f16x2(c0.x, c0.y);
            uint32_t ah1 = pack_f16x2(c2.x, c2.y);
            uint32_t ah2 = pack_f16x2(c1.x, c1.y);
            uint32_t ah3 = pack_f16x2(c3.x, c3.y);

            // stage fp16(x) for the fused pooling phase (packed pairs -> STS.64)
            {
                int col = kt * 8 + cb2 * 2;
                *reinterpret_cast<uint2*>(&stage[g * STAGE_ROW + col]) =
                    make_uint2(ah0, ah2);
                *reinterpret_cast<uint2*>(&stage[(g + 8) * STAGE_ROW + col]) =
                    make_uint2(ah1, ah3);
            }

            const uint4* bp = frag4 + kt * 256 + lane;
#pragma unroll
            for (int np = 0; np < 8; np++) {
                uint4 bb = bp[np * 32];             // one conflict-free LDS.128
                mma_f16(&acc[(2 * np    ) * 4], ah0, ah1, ah2, ah3, bb.x, bb.y);
                mma_f16(&acc[(2 * np + 1) * 4], ah0, ah1, ah2, ah3, bb.z, bb.w);
            }
        }

        // epilogue: s = sum_n tanh(h + b1) * W2  ->  z = exp(s + b2)
        float p0 = 0.0f, p1 = 0.0f;
#pragma unroll
        for (int nt = 0; nt < 16; nt++) {
            int n0 = nt * 8 + cbase;
            float2 w0 = pw[n0];
            float2 w1 = pw[n0 + 1];
            p0 += tanh_fast(acc[nt * 4 + 0] + w0.x) * w0.y;
            p0 += tanh_fast(acc[nt * 4 + 1] + w1.x) * w1.y;
            p1 += tanh_fast(acc[nt * 4 + 2] + w0.x) * w0.y;
            p1 += tanh_fast(acc[nt * 4 + 3] + w1.x) * w1.y;
        }
        p0 += __shfl_xor_sync(0xffffffffu, p0, 1);
        p0 += __shfl_xor_sync(0xffffffffu, p0, 2);
        p1 += __shfl_xor_sync(0xffffffffu, p1, 1);
        p1 += __shfl_xor_sync(0xffffffffu, p1, 2);

        const float z0 = __expf(p0 + bias2);        // row g
        const float z1 = __expf(p1 + bias2);        // row g + 8
        if ((lane & 3) == 0) {
            int r = tile * 16 + g;
            sw[r]     = z0;
            sw[r + 8] = z1;
        }
        __syncwarp();   // stage fully written by all lanes before cross-lane reads

        // ---- fused pooling: ctx[sid] += z * x_fp16, denom[sid] += z ----
        // lane reads one contiguous uint4 (4 half2) per token: cols lane*4..+3
        {
            float facc[8];
#pragma unroll
            for (int j = 0; j < 8; j++) facc[j] = 0.0f;
            float zsum = 0.0f;
            int cur = __shfl_sync(0xffffffffu, sgid, 0);
            const uint4* srow = reinterpret_cast<const uint4*>(stage) + lane;

#pragma unroll 1
            for (int tok = 0; tok < 16; tok++) {
                int sid_t = __shfl_sync(0xffffffffu, sgid, tok);
                float zt = (tok < 8)
                    ? __shfl_sync(0xffffffffu, z0, tok * 4)
                    : __shfl_sync(0xffffffffu, z1, (tok - 8) * 4);
                if (sid_t != cur) {
                    // flush previous segment group
                    float* cp = ctx + (size_t)cur * D_IN;
#pragma unroll
                    for (int j = 0; j < 4; j++) {
                        atomicAdd(cp + fmap[j],     facc[2 * j]);
                        atomicAdd(cp + fmap[j] + 1, facc[2 * j + 1]);
                        facc[2 * j] = 0.0f; facc[2 * j + 1] = 0.0f;
                    }
                    if (lane == 0) atomicAdd(&g_denom[cur], zsum);
                    zsum = 0.0f;
                    cur = sid_t;
                }
                zsum += zt;
                uint4 v = srow[tok * (STAGE_ROW / 4)];   // one LDS.128, conflict-free
                float2 f0 = __half22float2(*reinterpret_cast<const __half2*>(&v.x));
                float2 f1 = __half22float2(*reinterpret_cast<const __half2*>(&v.y));
                float2 f2 = __half22float2(*reinterpret_cast<const __half2*>(&v.z));
                float2 f3 = __half22float2(*reinterpret_cast<const __half2*>(&v.w));
                facc[0] += zt * f0.x;  facc[1] += zt * f0.y;
                facc[2] += zt * f1.x;  facc[3] += zt * f1.y;
                facc[4] += zt * f2.x;  facc[5] += zt * f2.y;
                facc[6] += zt * f3.x;  facc[7] += zt * f3.y;
            }
            // final flush
            float* cp = ctx + (size_t)cur * D_IN;
#pragma unroll
            for (int j = 0; j < 4; j++) {
                atomicAdd(cp + fmap[j],     facc[2 * j]);
                atomicAdd(cp + fmap[j] + 1, facc[2 * j + 1]);
            }
            if (lane == 0) atomicAdd(&g_denom[cur], zsum);
        }
        __syncwarp();   // stage fully consumed before next iteration overwrites
    }
}

// ---------------------------------------------------------------------------
// Pass 2a: attention_weights[i] = z[i] / denom[seg[i]]
// ---------------------------------------------------------------------------
__global__ __launch_bounds__(256)
void norm_w_kernel(float* __restrict__ sw, const int* __restrict__ seg) {
    int i = blockIdx.x * blockDim.x + threadIdx.x;
    if (i >= N_TOK) return;
    float d = __ldg(&g_denom[__ldg(seg + i)]);
    sw[i] = sw[i] / d;
}

// ---------------------------------------------------------------------------
// Pass 2b: ctx[b,:] /= denom[b]   (empty segment -> 0, matching segment_sum)
// ---------------------------------------------------------------------------
__global__ __launch_bounds__(256)
void norm_ctx_kernel(float* __restrict__ ctx) {
    int i = blockIdx.x * blockDim.x + threadIdx.x;
    if (i >= B_SEG * D_IN) return;
    float d = g_denom[i >> 8];
    float v = ctx[i];
    ctx[i] = (d > 0.0f) ? v / d : 0.0f;
}

// ---------------------------------------------------------------------------
// launch: outputs are [context_vectors (B*D)] then [attention_weights (N)]
// ---------------------------------------------------------------------------
extern "C" void kernel_launch(void* const* d_in, const int* in_sizes, int n_in,
                              void* d_out, int out_size) {
    const float* x   = (const float*)d_in[0];
    const int*   seg = (const int*)d_in[1];
    const float* W1  = (const float*)d_in[2];
    const float* b1  = (const float*)d_in[3];
    const float* W2  = (const float*)d_in[4];
    const float* b2  = (const float*)d_in[5];

    float* ctx = (float*)d_out;                       // [B, D]
    float* sw  = ctx + (size_t)B_SEG * D_IN;          // [N] : z then weights

    cudaFuncSetAttribute(logits_pool_kernel,
                         cudaFuncAttributeMaxDynamicSharedMemorySize, SMEM_LG);

    zero_kernel<<<(B_SEG * D_IN + 511) / 512, 512>>>(ctx);
    logits_pool_kernel<<<GRID_LG, 512, SMEM_LG>>>(x, seg, W1, b1, W2, b2, sw, ctx);
    norm_w_kernel<<<N_TOK / 256, 256>>>(sw, seg);
    norm_ctx_kernel<<<(B_SEG * D_IN) / 256, 256>>>(ctx);
}